// round 2
// baseline (speedup 1.0000x reference)
#include <cuda_runtime.h>

#define BB 8
#define DD 128
#define HH 256
#define WW 256
#define HWW 65536
#define TT 16
#define HCC 28
#define NPB 784
#define NN 6272
#define PP 29
#define QQ 12
#define COLSZ 6285

#define LABELS_OFF ((long long)NN * COLSZ)
#define MASK_OFF   (2LL * NN * COLSZ)
#define QLT_OFF    (2LL * NN * COLSZ + NN)

// Offsets in exact numpy enumeration order. .x added to x-coord, .y to y-coord.
__constant__ int2 c_pos[PP] = {
    {-3,0},
    {-2,-2},{-2,-1},{-2,0},{-2,1},{-2,2},
    {-1,-2},{-1,-1},{-1,0},{-1,1},{-1,2},
    {0,-3},{0,-2},{0,-1},{0,0},{0,1},{0,2},{0,3},
    {1,-2},{1,-1},{1,0},{1,1},{1,2},
    {2,-2},{2,-1},{2,0},{2,1},{2,2},
    {3,0}
};
__constant__ int2 c_neg[QQ] = {
    {-8,0},{-6,-4},{-6,4},{-4,-6},{-4,6},
    {0,-8},{0,8},
    {4,-6},{4,6},{6,-4},{6,4},{8,0}
};

// Scratch (device globals: no allocations allowed)
__device__ int g_y1[NN], g_x1[NN];   // det1 samples (NOTE: reference swaps x/y!)
__device__ int g_yd[NN], g_xd[NN];   // det2 samples (distractors)
__device__ int g_x2[NN], g_y2[NN];   // unclamped xy2
__device__ __align__(16) float g_AT[DD * NN];  // s_des1, K-major [c][n]
__device__ __align__(16) float g_BT[DD * NN];  // distr,  K-major [c][q]

// ---------------------------------------------------------------------------
// Cell argmax sampling for det1 and det2 (first-max, row-major ii,jj order).
// CRITICAL: the reference unpacks _sample's (b, x, y, n) as (b, y1, x1, n),
// i.e. y1 = t + cx*d + jj  and  x1 = t + cy*d + ii  (swapped!).
// ---------------------------------------------------------------------------
__global__ void sample_kernel(const float* __restrict__ det1,
                              const float* __restrict__ det2) {
    int t = blockIdx.x * blockDim.x + threadIdx.x;
    if (t >= 2 * NN) return;
    const float* det = (t < NN) ? det1 : det2;
    int s = (t < NN) ? t : (t - NN);
    int b = s / NPB;
    int r = s - b * NPB;
    int cy = r / HCC;
    int cx = r - cy * HCC;
    const float* base = det + (long long)b * HWW + (TT + cy * 8) * WW + (TT + cx * 8);
    float best = -__int_as_float(0x7f800000);  // -inf
    int bi = 0, bj = 0;
    #pragma unroll
    for (int ii = 0; ii < 8; ii++) {
        #pragma unroll
        for (int jj = 0; jj < 8; jj++) {
            float v = base[ii * WW + jj];
            if (v > best) { best = v; bi = ii; bj = jj; }
        }
    }
    // Reference swap: "y1" receives the x-array, "x1" receives the y-array.
    int y = TT + cx * 8 + bj;
    int x = TT + cy * 8 + bi;
    if (t < NN) { g_y1[s] = y; g_x1[s] = x; }
    else        { g_yd[s] = y; g_xd[s] = x; }
}

// ---------------------------------------------------------------------------
// Gather distractor descriptors into K-major matrix
// ---------------------------------------------------------------------------
__global__ void gather_distr_kernel(const float* __restrict__ des2) {
    int s = blockIdx.x;
    int c = threadIdx.x;
    int b = s / NPB;
    int y = g_yd[s], x = g_xd[s];
    g_BT[c * NN + s] = des2[((b * DD + c) * HH + y) * WW + x];
}

// ---------------------------------------------------------------------------
// Per-sample: gather s_des1, xy2+mask, pos scores (argmax), neg scores, qlt
// 128 threads/block = 4 warps; lane handles channels {l, l+32, l+64, l+96}
// ---------------------------------------------------------------------------
__global__ void score_kernel(const float* __restrict__ des1,
                             const float* __restrict__ des2,
                             const float* __restrict__ qlt1,
                             const float* __restrict__ qlt2,
                             const float* __restrict__ aflow,
                             float* __restrict__ out) {
    int s = blockIdx.x;
    int c = threadIdx.x;
    int b = s / NPB;
    __shared__ float sdes[128];
    __shared__ float spall[PP];
    __shared__ int sxy[2];

    int y1 = g_y1[s], x1 = g_x1[s];
    float v = des1[((b * DD + c) * HH + y1) * WW + x1];
    sdes[c] = v;
    g_AT[c * NN + s] = v;

    if (c == 0) {
        float ax = aflow[((b * 2 + 0) * HH + y1) * WW + x1];
        float ay = aflow[((b * 2 + 1) * HH + y1) * WW + x1];
        int xi = (int)(ax + 0.5f);   // trunc toward zero, matches astype(int32)
        int yi = (int)(ay + 0.5f);
        sxy[0] = xi; sxy[1] = yi;
        g_x2[s] = xi; g_y2[s] = yi;
        out[MASK_OFF + s] = (xi >= 0 && yi >= 0 && xi < WW && yi < HH) ? 1.0f : 0.0f;
    }
    __syncthreads();

    int x2 = sxy[0], y2 = sxy[1];
    int w = c >> 5, l = c & 31;
    float a0 = sdes[l], a1 = sdes[l + 32], a2 = sdes[l + 64], a3 = sdes[l + 96];
    const float* d2b = des2 + (long long)b * DD * HWW;

    for (int p = w; p < PP; p += 4) {
        int xx = min(max(x2 + c_pos[p].x, 0), WW - 1);
        int yy = min(max(y2 + c_pos[p].y, 0), HH - 1);
        const float* ptr = d2b + yy * WW + xx;
        float sum = a0 * ptr[(long long)l * HWW]
                  + a1 * ptr[(long long)(l + 32) * HWW]
                  + a2 * ptr[(long long)(l + 64) * HWW]
                  + a3 * ptr[(long long)(l + 96) * HWW];
        #pragma unroll
        for (int o = 16; o > 0; o >>= 1) sum += __shfl_down_sync(0xffffffffu, sum, o);
        if (l == 0) spall[p] = sum;
    }
    for (int q = w; q < QQ; q += 4) {
        int xx = min(max(x2 + c_neg[q].x, 0), WW - 1);
        int yy = min(max(y2 + c_neg[q].y, 0), HH - 1);
        const float* ptr = d2b + yy * WW + xx;
        float sum = a0 * ptr[(long long)l * HWW]
                  + a1 * ptr[(long long)(l + 32) * HWW]
                  + a2 * ptr[(long long)(l + 64) * HWW]
                  + a3 * ptr[(long long)(l + 96) * HWW];
        #pragma unroll
        for (int o = 16; o > 0; o >>= 1) sum += __shfl_down_sync(0xffffffffu, sum, o);
        if (l == 0) out[(long long)s * COLSZ + 1 + q] = sum;
    }
    __syncthreads();

    if (c == 0) {
        float best = spall[0]; int bp = 0;
        #pragma unroll
        for (int p = 1; p < PP; p++) {
            if (spall[p] > best) { best = spall[p]; bp = p; }  // first-max
        }
        out[(long long)s * COLSZ] = best;
        int selx = min(max(x2 + c_pos[bp].x, 0), WW - 1);
        int sely = min(max(y2 + c_pos[bp].y, 0), HH - 1);
        float q1 = qlt1[(long long)b * HWW + y1 * WW + x1];
        float q2 = qlt2[(long long)b * HWW + sely * WW + selx];
        out[QLT_OFF + s] = 0.5f * (q1 + q2);
    }
}

// ---------------------------------------------------------------------------
// dscores GEMM: scores[n][13+q] = dot(s_des1[n], distr[q]) with dis2 mask.
// 128x128 tile, 8x8 per thread (split 4+4), K chunks of 32, K-major globals.
// ---------------------------------------------------------------------------
__global__ void __launch_bounds__(256) gemm_kernel(float* __restrict__ out) {
    __shared__ float As[32][132];
    __shared__ float Bs[32][132];
    int m0 = blockIdx.y * 128, n0 = blockIdx.x * 128;
    int tid = threadIdx.x;
    int tx = tid & 15, ty = tid >> 4;

    float acc[8][8];
    #pragma unroll
    for (int i = 0; i < 8; i++)
        #pragma unroll
        for (int j = 0; j < 8; j++) acc[i][j] = 0.0f;

    for (int kc = 0; kc < 4; kc++) {
        #pragma unroll
        for (int i = 0; i < 4; i++) {
            int idx = tid + 256 * i;
            int k = idx >> 5;
            int c4 = (idx & 31) << 2;
            *(float4*)&As[k][c4] = *(const float4*)&g_AT[(kc * 32 + k) * NN + m0 + c4];
            *(float4*)&Bs[k][c4] = *(const float4*)&g_BT[(kc * 32 + k) * NN + n0 + c4];
        }
        __syncthreads();
        #pragma unroll
        for (int k = 0; k < 32; k++) {
            float4 t0 = *(const float4*)&As[k][ty * 4];
            float4 t1 = *(const float4*)&As[k][64 + ty * 4];
            float4 t2 = *(const float4*)&Bs[k][tx * 4];
            float4 t3 = *(const float4*)&Bs[k][64 + tx * 4];
            float a[8] = {t0.x, t0.y, t0.z, t0.w, t1.x, t1.y, t1.z, t1.w};
            float bv[8] = {t2.x, t2.y, t2.z, t2.w, t3.x, t3.y, t3.z, t3.w};
            #pragma unroll
            for (int i = 0; i < 8; i++)
                #pragma unroll
                for (int j = 0; j < 8; j++)
                    acc[i][j] = fmaf(a[i], bv[j], acc[i][j]);
        }
        __syncthreads();
    }

    // Epilogue: dis2 masking + store
    int rows[8], cols[8];
    #pragma unroll
    for (int i = 0; i < 4; i++) {
        rows[i]     = m0 + ty * 4 + i;
        rows[4 + i] = m0 + 64 + ty * 4 + i;
        cols[i]     = n0 + tx * 4 + i;
        cols[4 + i] = n0 + 64 + tx * 4 + i;
    }
    int rx[8], ry[8], rb[8], qx[8], qy[8], qb[8];
    #pragma unroll
    for (int i = 0; i < 8; i++) {
        rx[i] = g_x2[rows[i]]; ry[i] = g_y2[rows[i]]; rb[i] = rows[i] / NPB;
        qx[i] = g_xd[cols[i]]; qy[i] = g_yd[cols[i]]; qb[i] = cols[i] / NPB;
    }
    #pragma unroll
    for (int i = 0; i < 8; i++) {
        long long rbase = (long long)rows[i] * COLSZ + 13;
        #pragma unroll
        for (int j = 0; j < 8; j++) {
            int dx = qx[j] - rx[i];
            int dy = qy[j] - ry[i];
            int dis2 = dx * dx + dy * dy + ((qb[j] != rb[i]) ? 9 : 0);
            out[rbase + cols[j]] = (dis2 < 9) ? 0.0f : acc[i][j];
        }
    }
}

// ---------------------------------------------------------------------------
// labels: one-hot first column, float 1.0/0.0
// ---------------------------------------------------------------------------
__global__ void labels_kernel(float* __restrict__ out) {
    int row = blockIdx.y;
    int j = blockIdx.x * blockDim.x + threadIdx.x;
    if (j < COLSZ) {
        out[LABELS_OFF + (long long)row * COLSZ + j] = (j == 0) ? 1.0f : 0.0f;
    }
}

extern "C" void kernel_launch(void* const* d_in, const int* in_sizes, int n_in,
                              void* d_out, int out_size) {
    const float* des1  = (const float*)d_in[0];
    const float* det1  = (const float*)d_in[1];
    const float* qlt1  = (const float*)d_in[2];
    const float* des2  = (const float*)d_in[3];
    const float* det2  = (const float*)d_in[4];
    const float* qlt2  = (const float*)d_in[5];
    const float* aflow = (const float*)d_in[6];
    float* out = (float*)d_out;

    sample_kernel<<<(2 * NN + 255) / 256, 256>>>(det1, det2);
    gather_distr_kernel<<<NN, 128>>>(des2);
    score_kernel<<<NN, 128>>>(des1, des2, qlt1, qlt2, aflow, out);
    gemm_kernel<<<dim3(49, 49), 256>>>(out);
    labels_kernel<<<dim3((COLSZ + 255) / 256, NN), 256>>>(out);
}

// round 3
// speedup vs baseline: 1.0545x; 1.0545x over previous
#include <cuda_runtime.h>

#define BB 8
#define DD 128
#define HH 256
#define WW 256
#define HWW 65536
#define TT 16
#define HCC 28
#define NPB 784
#define NN 6272
#define PP 29
#define QQ 12
#define COLSZ 6285

#define LABELS_OFF ((long long)NN * COLSZ)
#define MASK_OFF   (2LL * NN * COLSZ)
#define QLT_OFF    (2LL * NN * COLSZ + NN)

// Offsets in exact numpy enumeration order. .x added to x-coord, .y to y-coord.
__constant__ int2 c_pos[PP] = {
    {-3,0},
    {-2,-2},{-2,-1},{-2,0},{-2,1},{-2,2},
    {-1,-2},{-1,-1},{-1,0},{-1,1},{-1,2},
    {0,-3},{0,-2},{0,-1},{0,0},{0,1},{0,2},{0,3},
    {1,-2},{1,-1},{1,0},{1,1},{1,2},
    {2,-2},{2,-1},{2,0},{2,1},{2,2},
    {3,0}
};
__constant__ int2 c_neg[QQ] = {
    {-8,0},{-6,-4},{-6,4},{-4,-6},{-4,6},
    {0,-8},{0,8},
    {4,-6},{4,6},{6,-4},{6,4},{8,0}
};

// Scratch (device globals: no allocations allowed)
__device__ int g_y1[NN], g_x1[NN];   // det1 samples (reference swaps x/y!)
__device__ int g_yd[NN], g_xd[NN];   // det2 samples (distractors)
__device__ int g_x2[NN], g_y2[NN];   // unclamped xy2
__device__ __align__(16) float g_AT[DD * NN];   // s_des1, K-major [c][n]
__device__ __align__(16) float g_BT[DD * NN];   // distr,  K-major [c][q]
__device__ __align__(16) float g_des2t[(long long)BB * HWW * DD];  // des2 NHWC

// ---------------------------------------------------------------------------
// Cell argmax sampling (first-max). Reference unpacks _sample's (b,x,y) as
// (b,y1,x1): y1 = t + cx*8 + jj, x1 = t + cy*8 + ii (swapped).
// ---------------------------------------------------------------------------
__global__ void sample_kernel(const float* __restrict__ det1,
                              const float* __restrict__ det2) {
    int t = blockIdx.x * blockDim.x + threadIdx.x;
    if (t >= 2 * NN) return;
    const float* det = (t < NN) ? det1 : det2;
    int s = (t < NN) ? t : (t - NN);
    int b = s / NPB;
    int r = s - b * NPB;
    int cy = r / HCC;
    int cx = r - cy * HCC;
    const float* base = det + (long long)b * HWW + (TT + cy * 8) * WW + (TT + cx * 8);
    float best = -__int_as_float(0x7f800000);
    int bi = 0, bj = 0;
    #pragma unroll
    for (int ii = 0; ii < 8; ii++) {
        #pragma unroll
        for (int jj = 0; jj < 8; jj++) {
            float v = base[ii * WW + jj];
            if (v > best) { best = v; bi = ii; bj = jj; }
        }
    }
    int y = TT + cx * 8 + bj;   // reference swap
    int x = TT + cy * 8 + bi;
    if (t < NN) { g_y1[s] = y; g_x1[s] = x; }
    else        { g_yd[s] = y; g_xd[s] = x; }
}

// ---------------------------------------------------------------------------
// Transpose des2 (B,C,H,W) -> NHWC g_des2t[(b*HWW+pix)*128 + c].
// Block = 256 thr, handles 128 chans x 32 pixels. Conflict-free smem tile.
// ---------------------------------------------------------------------------
__global__ void __launch_bounds__(256) transpose_kernel(const float* __restrict__ des2) {
    __shared__ float t[128][33];
    int b = blockIdx.y;
    int p0 = blockIdx.x * 32;
    int w = threadIdx.x >> 5, l = threadIdx.x & 31;
    const float* src = des2 + (long long)b * DD * HWW + p0;
    #pragma unroll
    for (int i = 0; i < 16; i++) {
        int cch = w + 8 * i;
        t[cch][l] = src[(long long)cch * HWW + l];      // coalesced 128B
    }
    __syncthreads();
    float* dst = g_des2t + ((long long)b * HWW + p0) * DD;
    #pragma unroll
    for (int j = 0; j < 4; j++) {
        int p = w + 8 * j;
        #pragma unroll
        for (int u = 0; u < 4; u++) {
            dst[p * DD + u * 32 + l] = t[u * 32 + l][p];  // coalesced 128B stores
        }
    }
}

// ---------------------------------------------------------------------------
// Gather distractor descriptors into K-major matrix (from NHWC copy)
// ---------------------------------------------------------------------------
__global__ void gather_distr_kernel() {
    int s = blockIdx.x;
    int c = threadIdx.x;
    int b = s / NPB;
    long long pix = (long long)b * HWW + g_yd[s] * WW + g_xd[s];
    g_BT[c * NN + s] = g_des2t[pix * DD + c];
}

// ---------------------------------------------------------------------------
// Per-sample: gather s_des1, xy2+mask, pos scores (argmax), neg scores, qlt,
// labels cols 0..12. Each warp computes full 128-dot per offset (coalesced
// 512B float4 reads from NHWC des2).
// ---------------------------------------------------------------------------
__global__ void score_kernel(const float* __restrict__ des1,
                             const float* __restrict__ qlt1,
                             const float* __restrict__ qlt2,
                             const float* __restrict__ aflow,
                             float* __restrict__ out) {
    int s = blockIdx.x;
    int c = threadIdx.x;
    int b = s / NPB;
    __shared__ float sdes[128];
    __shared__ float spall[32];
    __shared__ int sxy[2];

    int y1 = g_y1[s], x1 = g_x1[s];
    float v = des1[((b * DD + c) * HH + y1) * WW + x1];
    sdes[c] = v;
    g_AT[c * NN + s] = v;

    if (c == 0) {
        float ax = aflow[((b * 2 + 0) * HH + y1) * WW + x1];
        float ay = aflow[((b * 2 + 1) * HH + y1) * WW + x1];
        int xi = (int)(ax + 0.5f);   // trunc toward zero, matches astype(int32)
        int yi = (int)(ay + 0.5f);
        sxy[0] = xi; sxy[1] = yi;
        g_x2[s] = xi; g_y2[s] = yi;
        out[MASK_OFF + s] = (xi >= 0 && yi >= 0 && xi < WW && yi < HH) ? 1.0f : 0.0f;
    }
    if (c < 13) out[LABELS_OFF + (long long)s * COLSZ + c] = (c == 0) ? 1.0f : 0.0f;
    __syncthreads();

    int x2 = sxy[0], y2 = sxy[1];
    int w = c >> 5, l = c & 31;
    float4 a = *(const float4*)&sdes[l * 4];
    const float* dt = g_des2t + (long long)b * HWW * DD;

    for (int p = w; p < PP; p += 4) {
        int xx = min(max(x2 + c_pos[p].x, 0), WW - 1);
        int yy = min(max(y2 + c_pos[p].y, 0), HH - 1);
        float4 dv = *(const float4*)(dt + (yy * WW + xx) * DD + l * 4);
        float sum = a.x * dv.x + a.y * dv.y + a.z * dv.z + a.w * dv.w;
        #pragma unroll
        for (int o = 16; o > 0; o >>= 1) sum += __shfl_down_sync(0xffffffffu, sum, o);
        if (l == 0) spall[p] = sum;
    }
    for (int q = w; q < QQ; q += 4) {
        int xx = min(max(x2 + c_neg[q].x, 0), WW - 1);
        int yy = min(max(y2 + c_neg[q].y, 0), HH - 1);
        float4 dv = *(const float4*)(dt + (yy * WW + xx) * DD + l * 4);
        float sum = a.x * dv.x + a.y * dv.y + a.z * dv.z + a.w * dv.w;
        #pragma unroll
        for (int o = 16; o > 0; o >>= 1) sum += __shfl_down_sync(0xffffffffu, sum, o);
        if (l == 0) out[(long long)s * COLSZ + 1 + q] = sum;
    }
    __syncthreads();

    if (c == 0) {
        float best = spall[0]; int bp = 0;
        #pragma unroll
        for (int p = 1; p < PP; p++) {
            if (spall[p] > best) { best = spall[p]; bp = p; }  // first-max
        }
        out[(long long)s * COLSZ] = best;
        int selx = min(max(x2 + c_pos[bp].x, 0), WW - 1);
        int sely = min(max(y2 + c_pos[bp].y, 0), HH - 1);
        float q1 = qlt1[(long long)b * HWW + y1 * WW + x1];
        float q2 = qlt2[(long long)b * HWW + sely * WW + selx];
        out[QLT_OFF + s] = 0.5f * (q1 + q2);
    }
}

// ---------------------------------------------------------------------------
// dscores GEMM: software-pipelined (register-prefetch next K chunk).
// 128x128 tile, 8x8/thread, K chunks of 32. Epilogue: dis2 mask + labels=0.
// ---------------------------------------------------------------------------
__global__ void __launch_bounds__(256) gemm_kernel(float* __restrict__ out) {
    __shared__ float As[32][132];
    __shared__ float Bs[32][132];
    int m0 = blockIdx.y * 128, n0 = blockIdx.x * 128;
    int tid = threadIdx.x;
    int tx = tid & 15, ty = tid >> 4;

    float4 ra[4], rb[4];
    #pragma unroll
    for (int i = 0; i < 4; i++) {
        int idx = tid + 256 * i;
        int k = idx >> 5;
        int c4 = (idx & 31) << 2;
        ra[i] = *(const float4*)&g_AT[k * NN + m0 + c4];
        rb[i] = *(const float4*)&g_BT[k * NN + n0 + c4];
    }

    float acc[8][8];
    #pragma unroll
    for (int i = 0; i < 8; i++)
        #pragma unroll
        for (int j = 0; j < 8; j++) acc[i][j] = 0.0f;

    for (int kc = 0; kc < 4; kc++) {
        #pragma unroll
        for (int i = 0; i < 4; i++) {
            int idx = tid + 256 * i;
            int k = idx >> 5;
            int c4 = (idx & 31) << 2;
            *(float4*)&As[k][c4] = ra[i];
            *(float4*)&Bs[k][c4] = rb[i];
        }
        __syncthreads();
        if (kc < 3) {
            #pragma unroll
            for (int i = 0; i < 4; i++) {
                int idx = tid + 256 * i;
                int k = idx >> 5;
                int c4 = (idx & 31) << 2;
                ra[i] = *(const float4*)&g_AT[((kc + 1) * 32 + k) * NN + m0 + c4];
                rb[i] = *(const float4*)&g_BT[((kc + 1) * 32 + k) * NN + n0 + c4];
            }
        }
        #pragma unroll
        for (int k = 0; k < 32; k++) {
            float4 t0 = *(const float4*)&As[k][ty * 4];
            float4 t1 = *(const float4*)&As[k][64 + ty * 4];
            float4 t2 = *(const float4*)&Bs[k][tx * 4];
            float4 t3 = *(const float4*)&Bs[k][64 + tx * 4];
            float a[8] = {t0.x, t0.y, t0.z, t0.w, t1.x, t1.y, t1.z, t1.w};
            float bv[8] = {t2.x, t2.y, t2.z, t2.w, t3.x, t3.y, t3.z, t3.w};
            #pragma unroll
            for (int i = 0; i < 8; i++)
                #pragma unroll
                for (int j = 0; j < 8; j++)
                    acc[i][j] = fmaf(a[i], bv[j], acc[i][j]);
        }
        __syncthreads();
    }

    // Epilogue: dis2 masking + scores store + labels zeros
    int rows[8], cols[8];
    #pragma unroll
    for (int i = 0; i < 4; i++) {
        rows[i]     = m0 + ty * 4 + i;
        rows[4 + i] = m0 + 64 + ty * 4 + i;
        cols[i]     = n0 + tx * 4 + i;
        cols[4 + i] = n0 + 64 + tx * 4 + i;
    }
    int rx[8], ry[8], rb_[8], qx[8], qy[8], qb[8];
    #pragma unroll
    for (int i = 0; i < 8; i++) {
        rx[i] = g_x2[rows[i]]; ry[i] = g_y2[rows[i]]; rb_[i] = rows[i] / NPB;
        qx[i] = g_xd[cols[i]]; qy[i] = g_yd[cols[i]]; qb[i] = cols[i] / NPB;
    }
    #pragma unroll
    for (int i = 0; i < 8; i++) {
        long long sbase = (long long)rows[i] * COLSZ + 13;
        long long lbase = LABELS_OFF + sbase;
        #pragma unroll
        for (int j = 0; j < 8; j++) {
            int dx = qx[j] - rx[i];
            int dy = qy[j] - ry[i];
            int dis2 = dx * dx + dy * dy + ((qb[j] != rb_[i]) ? 9 : 0);
            out[sbase + cols[j]] = (dis2 < 9) ? 0.0f : acc[i][j];
            out[lbase + cols[j]] = 0.0f;
        }
    }
}

extern "C" void kernel_launch(void* const* d_in, const int* in_sizes, int n_in,
                              void* d_out, int out_size) {
    const float* des1  = (const float*)d_in[0];
    const float* det1  = (const float*)d_in[1];
    const float* qlt1  = (const float*)d_in[2];
    const float* des2  = (const float*)d_in[3];
    const float* det2  = (const float*)d_in[4];
    const float* qlt2  = (const float*)d_in[5];
    const float* aflow = (const float*)d_in[6];
    float* out = (float*)d_out;

    sample_kernel<<<(2 * NN + 255) / 256, 256>>>(det1, det2);
    transpose_kernel<<<dim3(HWW / 32, BB), 256>>>(des2);
    gather_distr_kernel<<<NN, 128>>>();
    score_kernel<<<NN, 128>>>(des1, qlt1, qlt2, aflow, out);
    gemm_kernel<<<dim3(49, 49), 256>>>(out);
}

// round 5
// speedup vs baseline: 1.4641x; 1.3884x over previous
#include <cuda_runtime.h>
#include <cstdint>

#define BB 8
#define DD 128
#define HH 256
#define WW 256
#define HWW 65536
#define TT 16
#define HCC 28
#define NPB 784
#define NN 6272
#define PP 29
#define QQ 12
#define COLSZ 6285
#define NPAD 6400   // B rows padded to 50*128

#define LABELS_OFF ((long long)NN * COLSZ)
#define MASK_OFF   (2LL * NN * COLSZ)
#define QLT_OFF    (2LL * NN * COLSZ + NN)

__device__ __forceinline__ float to_tf32(float x) {
    float r;
    asm("cvt.rna.tf32.f32 %0, %1;" : "=f"(r) : "f"(x));
    return r;
}

__device__ __forceinline__ void mma_tf32(float c[4], const uint32_t a[4], const uint32_t b[2]) {
    asm volatile(
        "mma.sync.aligned.m16n8k8.row.col.f32.tf32.tf32.f32 "
        "{%0,%1,%2,%3}, {%4,%5,%6,%7}, {%8,%9}, {%0,%1,%2,%3};"
        : "+f"(c[0]), "+f"(c[1]), "+f"(c[2]), "+f"(c[3])
        : "r"(a[0]), "r"(a[1]), "r"(a[2]), "r"(a[3]), "r"(b[0]), "r"(b[1]));
}

// ===================== problem constants =====================
__constant__ int2 c_pos[PP] = {
    {-3,0},
    {-2,-2},{-2,-1},{-2,0},{-2,1},{-2,2},
    {-1,-2},{-1,-1},{-1,0},{-1,1},{-1,2},
    {0,-3},{0,-2},{0,-1},{0,0},{0,1},{0,2},{0,3},
    {1,-2},{1,-1},{1,0},{1,1},{1,2},
    {2,-2},{2,-1},{2,0},{2,1},{2,2},
    {3,0}
};
__constant__ int2 c_neg[QQ] = {
    {-8,0},{-6,-4},{-6,4},{-4,-6},{-4,6},
    {0,-8},{0,8},
    {4,-6},{4,6},{6,-4},{6,4},{8,0}
};

__device__ int g_y1[NN], g_x1[NN];
__device__ int g_yd[NN], g_xd[NN];
__device__ int g_x2[NN], g_y2[NN];
__device__ __align__(16) float g_A[NN * DD];     // s_des1 row-major [n][k], tf32-rounded
__device__ __align__(16) float g_B[NPAD * DD];   // distr   row-major [q][k], tf32-rounded
__device__ __align__(16) float g_des2t[(long long)BB * HWW * DD];  // des2 NHWC

// ---------------------------------------------------------------------------
// Cell argmax sampling (first-max). Reference swaps x/y on unpack.
// ---------------------------------------------------------------------------
__global__ void sample_kernel(const float* __restrict__ det1,
                              const float* __restrict__ det2) {
    int t = blockIdx.x * blockDim.x + threadIdx.x;
    if (t >= 2 * NN) return;
    const float* det = (t < NN) ? det1 : det2;
    int s = (t < NN) ? t : (t - NN);
    int b = s / NPB;
    int r = s - b * NPB;
    int cy = r / HCC;
    int cx = r - cy * HCC;
    const float* base = det + (long long)b * HWW + (TT + cy * 8) * WW + (TT + cx * 8);
    float best = -__int_as_float(0x7f800000);
    int bi = 0, bj = 0;
    #pragma unroll
    for (int ii = 0; ii < 8; ii++) {
        #pragma unroll
        for (int jj = 0; jj < 8; jj++) {
            float v = base[ii * WW + jj];
            if (v > best) { best = v; bi = ii; bj = jj; }
        }
    }
    int y = TT + cx * 8 + bj;   // reference swap
    int x = TT + cy * 8 + bi;
    if (t < NN) { g_y1[s] = y; g_x1[s] = x; }
    else        { g_yd[s] = y; g_xd[s] = x; }
}

// ---------------------------------------------------------------------------
// Transpose des2 (B,C,H,W) -> NHWC
// ---------------------------------------------------------------------------
__global__ void __launch_bounds__(256) transpose_kernel(const float* __restrict__ des2) {
    __shared__ float t[128][33];
    int b = blockIdx.y;
    int p0 = blockIdx.x * 32;
    int w = threadIdx.x >> 5, l = threadIdx.x & 31;
    const float* src = des2 + (long long)b * DD * HWW + p0;
    #pragma unroll
    for (int i = 0; i < 16; i++) {
        int cch = w + 8 * i;
        t[cch][l] = src[(long long)cch * HWW + l];
    }
    __syncthreads();
    float* dst = g_des2t + ((long long)b * HWW + p0) * DD;
    #pragma unroll
    for (int j = 0; j < 4; j++) {
        int p = w + 8 * j;
        #pragma unroll
        for (int u = 0; u < 4; u++) {
            dst[p * DD + u * 32 + l] = t[u * 32 + l][p];
        }
    }
}

// ---------------------------------------------------------------------------
// Gather distractors row-major (tf32-rounded); zero-pad rows NN..NPAD
// ---------------------------------------------------------------------------
__global__ void gather_distr_kernel() {
    int s = blockIdx.x;
    int c = threadIdx.x;
    if (s >= NN) { g_B[s * DD + c] = 0.0f; return; }
    int b = s / NPB;
    long long pix = (long long)b * HWW + g_yd[s] * WW + g_xd[s];
    g_B[s * DD + c] = to_tf32(g_des2t[pix * DD + c]);
}

// ---------------------------------------------------------------------------
// Per-sample: s_des1 gather, xy2+mask, pos(argmax)/neg scores, qlt, labels 0..12
// ---------------------------------------------------------------------------
__global__ void score_kernel(const float* __restrict__ des1,
                             const float* __restrict__ qlt1,
                             const float* __restrict__ qlt2,
                             const float* __restrict__ aflow,
                             float* __restrict__ out) {
    int s = blockIdx.x;
    int c = threadIdx.x;
    int b = s / NPB;
    __shared__ float sdes[128];
    __shared__ float spall[32];
    __shared__ int sxy[2];

    int y1 = g_y1[s], x1 = g_x1[s];
    float v = des1[((b * DD + c) * HH + y1) * WW + x1];
    sdes[c] = v;
    g_A[s * DD + c] = to_tf32(v);

    if (c == 0) {
        float ax = aflow[((b * 2 + 0) * HH + y1) * WW + x1];
        float ay = aflow[((b * 2 + 1) * HH + y1) * WW + x1];
        int xi = (int)(ax + 0.5f);
        int yi = (int)(ay + 0.5f);
        sxy[0] = xi; sxy[1] = yi;
        g_x2[s] = xi; g_y2[s] = yi;
        out[MASK_OFF + s] = (xi >= 0 && yi >= 0 && xi < WW && yi < HH) ? 1.0f : 0.0f;
    }
    if (c < 13) out[LABELS_OFF + (long long)s * COLSZ + c] = (c == 0) ? 1.0f : 0.0f;
    __syncthreads();

    int x2 = sxy[0], y2 = sxy[1];
    int w = c >> 5, l = c & 31;
    float4 a = *(const float4*)&sdes[l * 4];
    const float* dt = g_des2t + (long long)b * HWW * DD;

    for (int p = w; p < PP; p += 4) {
        int xx = min(max(x2 + c_pos[p].x, 0), WW - 1);
        int yy = min(max(y2 + c_pos[p].y, 0), HH - 1);
        float4 dv = *(const float4*)(dt + (yy * WW + xx) * DD + l * 4);
        float sum = a.x * dv.x + a.y * dv.y + a.z * dv.z + a.w * dv.w;
        #pragma unroll
        for (int o = 16; o > 0; o >>= 1) sum += __shfl_down_sync(0xffffffffu, sum, o);
        if (l == 0) spall[p] = sum;
    }
    for (int q = w; q < QQ; q += 4) {
        int xx = min(max(x2 + c_neg[q].x, 0), WW - 1);
        int yy = min(max(y2 + c_neg[q].y, 0), HH - 1);
        float4 dv = *(const float4*)(dt + (yy * WW + xx) * DD + l * 4);
        float sum = a.x * dv.x + a.y * dv.y + a.z * dv.z + a.w * dv.w;
        #pragma unroll
        for (int o = 16; o > 0; o >>= 1) sum += __shfl_down_sync(0xffffffffu, sum, o);
        if (l == 0) out[(long long)s * COLSZ + 1 + q] = sum;
    }
    __syncthreads();

    if (c == 0) {
        float best = spall[0]; int bp = 0;
        #pragma unroll
        for (int p = 1; p < PP; p++) {
            if (spall[p] > best) { best = spall[p]; bp = p; }
        }
        out[(long long)s * COLSZ] = best;
        int selx = min(max(x2 + c_pos[bp].x, 0), WW - 1);
        int sely = min(max(y2 + c_pos[bp].y, 0), HH - 1);
        float q1 = qlt1[(long long)b * HWW + y1 * WW + x1];
        float q2 = qlt2[(long long)b * HWW + sely * WW + selx];
        out[QLT_OFF + s] = 0.5f * (q1 + q2);
    }
}

// ---------------------------------------------------------------------------
// dscores GEMM via mma.sync tf32 (m16n8k8). CTA tile 128x128, 8 warps 2x4,
// warp tile 64x32 (4x4 mma tiles). K chunks of 32 with register prefetch.
// Epilogue: dis2 mask + scores + labels zeros.
// ---------------------------------------------------------------------------
__global__ void __launch_bounds__(256) gemm_kernel(float* __restrict__ out) {
    __shared__ float As[128][36];   // [m][k], stride 36: frag loads conflict-free
    __shared__ float Bs[128][36];   // [n][k]
    __shared__ int sqx[128], sqy[128], sqb[128];

    int tid = threadIdx.x;
    int wid = tid >> 5, lane = tid & 31;
    int gid = lane >> 2, t4 = lane & 3;
    int wr = wid >> 2, wc = wid & 3;
    int m0 = blockIdx.y * 128, n0 = blockIdx.x * 128;

    if (tid < 128) {
        int q = n0 + tid;
        int qx = 0, qy = 0, qb = 0;
        if (q < NN) { qx = g_xd[q]; qy = g_yd[q]; qb = q / NPB; }
        sqx[tid] = qx; sqy[tid] = qy; sqb[tid] = qb;
    }

    float4 ra[4], rbv[4];
    #pragma unroll
    for (int i = 0; i < 4; i++) {
        int idx = tid + 256 * i;
        int row = idx >> 3, c4 = idx & 7;
        ra[i]  = *(const float4*)&g_A[(m0 + row) * DD + c4 * 4];
        rbv[i] = *(const float4*)&g_B[(n0 + row) * DD + c4 * 4];
    }

    float acc[4][4][4];
    #pragma unroll
    for (int i = 0; i < 4; i++)
        #pragma unroll
        for (int j = 0; j < 4; j++)
            #pragma unroll
            for (int c = 0; c < 4; c++) acc[i][j][c] = 0.0f;

    for (int kc = 0; kc < 4; kc++) {
        #pragma unroll
        for (int i = 0; i < 4; i++) {
            int idx = tid + 256 * i;
            int row = idx >> 3, c4 = idx & 7;
            *(float4*)&As[row][c4 * 4] = ra[i];
            *(float4*)&Bs[row][c4 * 4] = rbv[i];
        }
        __syncthreads();
        if (kc < 3) {
            #pragma unroll
            for (int i = 0; i < 4; i++) {
                int idx = tid + 256 * i;
                int row = idx >> 3, c4 = idx & 7;
                ra[i]  = *(const float4*)&g_A[(m0 + row) * DD + (kc + 1) * 32 + c4 * 4];
                rbv[i] = *(const float4*)&g_B[(n0 + row) * DD + (kc + 1) * 32 + c4 * 4];
            }
        }
        #pragma unroll
        for (int kk = 0; kk < 4; kk++) {
            int kb = kk * 8;
            uint32_t af[4][4], bf[4][2];
            #pragma unroll
            for (int i = 0; i < 4; i++) {
                int r = wr * 64 + i * 16 + gid;
                af[i][0] = __float_as_uint(As[r][kb + t4]);
                af[i][1] = __float_as_uint(As[r + 8][kb + t4]);
                af[i][2] = __float_as_uint(As[r][kb + t4 + 4]);
                af[i][3] = __float_as_uint(As[r + 8][kb + t4 + 4]);
            }
            #pragma unroll
            for (int j = 0; j < 4; j++) {
                int nr = wc * 32 + j * 8 + gid;
                bf[j][0] = __float_as_uint(Bs[nr][kb + t4]);
                bf[j][1] = __float_as_uint(Bs[nr][kb + t4 + 4]);
            }
            #pragma unroll
            for (int i = 0; i < 4; i++)
                #pragma unroll
                for (int j = 0; j < 4; j++)
                    mma_tf32(acc[i][j], af[i], bf[j]);
        }
        __syncthreads();
    }

    // Epilogue: fused dis2 mask + scores + labels
    #pragma unroll
    for (int i = 0; i < 4; i++) {
        int r0 = m0 + wr * 64 + i * 16 + gid;
        int r1 = r0 + 8;
        int rx0 = g_x2[r0], ry0 = g_y2[r0], rb0 = r0 / NPB;
        int rx1 = g_x2[r1], ry1 = g_y2[r1], rb1 = r1 / NPB;
        long long s0 = (long long)r0 * COLSZ + 13;
        long long s1 = (long long)r1 * COLSZ + 13;
        #pragma unroll
        for (int j = 0; j < 4; j++) {
            int c0 = wc * 32 + j * 8 + t4 * 2;   // local col
            int c1 = c0 + 1;
            long long q0 = n0 + c0, q1 = n0 + c1;
            if (q0 < NN) {
                int dx, dy, d2;
                dx = sqx[c0] - rx0; dy = sqy[c0] - ry0;
                d2 = dx * dx + dy * dy + ((sqb[c0] != rb0) ? 9 : 0);
                out[s0 + q0] = (d2 < 9) ? 0.0f : acc[i][j][0];
                out[LABELS_OFF + s0 + q0] = 0.0f;
                dx = sqx[c0] - rx1; dy = sqy[c0] - ry1;
                d2 = dx * dx + dy * dy + ((sqb[c0] != rb1) ? 9 : 0);
                out[s1 + q0] = (d2 < 9) ? 0.0f : acc[i][j][2];
                out[LABELS_OFF + s1 + q0] = 0.0f;
            }
            if (q1 < NN) {
                int dx, dy, d2;
                dx = sqx[c1] - rx0; dy = sqy[c1] - ry0;
                d2 = dx * dx + dy * dy + ((sqb[c1] != rb0) ? 9 : 0);
                out[s0 + q1] = (d2 < 9) ? 0.0f : acc[i][j][1];
                out[LABELS_OFF + s0 + q1] = 0.0f;
                dx = sqx[c1] - rx1; dy = sqy[c1] - ry1;
                d2 = dx * dx + dy * dy + ((sqb[c1] != rb1) ? 9 : 0);
                out[s1 + q1] = (d2 < 9) ? 0.0f : acc[i][j][3];
                out[LABELS_OFF + s1 + q1] = 0.0f;
            }
        }
    }
}

extern "C" void kernel_launch(void* const* d_in, const int* in_sizes, int n_in,
                              void* d_out, int out_size) {
    const float* des1  = (const float*)d_in[0];
    const float* det1  = (const float*)d_in[1];
    const float* qlt1  = (const float*)d_in[2];
    const float* des2  = (const float*)d_in[3];
    const float* det2  = (const float*)d_in[4];
    const float* qlt2  = (const float*)d_in[5];
    const float* aflow = (const float*)d_in[6];
    float* out = (float*)d_out;

    sample_kernel<<<(2 * NN + 255) / 256, 256>>>(det1, det2);
    transpose_kernel<<<dim3(HWW / 32, BB), 256>>>(des2);
    gather_distr_kernel<<<NPAD, 128>>>();
    score_kernel<<<NN, 128>>>(des1, qlt1, qlt2, aflow, out);
    gemm_kernel<<<dim3(50, 49), 256>>>(out);
}

// round 6
// speedup vs baseline: 1.7648x; 1.2054x over previous
#include <cuda_runtime.h>
#include <cstdint>

#define BB 8
#define DD 128
#define HH 256
#define WW 256
#define HWW 65536
#define TT 16
#define HCC 28
#define NPB 784
#define NN 6272
#define PP 29
#define QQ 12
#define COLSZ 6285

#define LABELS_OFF ((long long)NN * COLSZ)
#define MASK_OFF   (2LL * NN * COLSZ)
#define QLT_OFF    (2LL * NN * COLSZ + NN)

__device__ __forceinline__ float to_tf32(float x) {
    float r;
    asm("cvt.rna.tf32.f32 %0, %1;" : "=f"(r) : "f"(x));
    return r;
}

__device__ __forceinline__ void mma_tf32(float c[4], const uint32_t a[4], const uint32_t b[2]) {
    asm volatile(
        "mma.sync.aligned.m16n8k8.row.col.f32.tf32.tf32.f32 "
        "{%0,%1,%2,%3}, {%4,%5,%6,%7}, {%8,%9}, {%0,%1,%2,%3};"
        : "+f"(c[0]), "+f"(c[1]), "+f"(c[2]), "+f"(c[3])
        : "r"(a[0]), "r"(a[1]), "r"(a[2]), "r"(a[3]), "r"(b[0]), "r"(b[1]));
}

// ===================== problem constants =====================
__constant__ int2 c_pos[PP] = {
    {-3,0},
    {-2,-2},{-2,-1},{-2,0},{-2,1},{-2,2},
    {-1,-2},{-1,-1},{-1,0},{-1,1},{-1,2},
    {0,-3},{0,-2},{0,-1},{0,0},{0,1},{0,2},{0,3},
    {1,-2},{1,-1},{1,0},{1,1},{1,2},
    {2,-2},{2,-1},{2,0},{2,1},{2,2},
    {3,0}
};
__constant__ int2 c_neg[QQ] = {
    {-8,0},{-6,-4},{-6,4},{-4,-6},{-4,6},
    {0,-8},{0,8},
    {4,-6},{4,6},{6,-4},{6,4},{8,0}
};

__device__ int g_y1[NN], g_x1[NN];
__device__ int g_yd[NN], g_xd[NN];
__device__ int g_x2[NN], g_y2[NN];
__device__ __align__(16) float g_A[NN * DD];     // s_des1 row-major [n][k], tf32-rounded
__device__ __align__(16) float g_B[NN * DD];     // distr   row-major [q][k], tf32-rounded
__device__ __align__(16) float g_des2t[(long long)BB * HWW * DD];  // des2 NHWC

// ---------------------------------------------------------------------------
// Cell argmax sampling (first-max). Reference swaps x/y on unpack.
// ---------------------------------------------------------------------------
__global__ void sample_kernel(const float* __restrict__ det1,
                              const float* __restrict__ det2) {
    int t = blockIdx.x * blockDim.x + threadIdx.x;
    if (t >= 2 * NN) return;
    const float* det = (t < NN) ? det1 : det2;
    int s = (t < NN) ? t : (t - NN);
    int b = s / NPB;
    int r = s - b * NPB;
    int cy = r / HCC;
    int cx = r - cy * HCC;
    const float* base = det + (long long)b * HWW + (TT + cy * 8) * WW + (TT + cx * 8);
    float best = -__int_as_float(0x7f800000);
    int bi = 0, bj = 0;
    #pragma unroll
    for (int ii = 0; ii < 8; ii++) {
        #pragma unroll
        for (int jj = 0; jj < 8; jj++) {
            float v = base[ii * WW + jj];
            if (v > best) { best = v; bi = ii; bj = jj; }
        }
    }
    int y = TT + cx * 8 + bj;   // reference swap
    int x = TT + cy * 8 + bi;
    if (t < NN) { g_y1[s] = y; g_x1[s] = x; }
    else        { g_yd[s] = y; g_xd[s] = x; }
}

// ---------------------------------------------------------------------------
// Transpose des2 (B,C,H,W) -> NHWC
// ---------------------------------------------------------------------------
__global__ void __launch_bounds__(256) transpose_kernel(const float* __restrict__ des2) {
    __shared__ float t[128][33];
    int b = blockIdx.y;
    int p0 = blockIdx.x * 32;
    int w = threadIdx.x >> 5, l = threadIdx.x & 31;
    const float* src = des2 + (long long)b * DD * HWW + p0;
    #pragma unroll
    for (int i = 0; i < 16; i++) {
        int cch = w + 8 * i;
        t[cch][l] = src[(long long)cch * HWW + l];
    }
    __syncthreads();
    float* dst = g_des2t + ((long long)b * HWW + p0) * DD;
    #pragma unroll
    for (int j = 0; j < 4; j++) {
        int p = w + 8 * j;
        #pragma unroll
        for (int u = 0; u < 4; u++) {
            dst[p * DD + u * 32 + l] = t[u * 32 + l][p];
        }
    }
}

// ---------------------------------------------------------------------------
// Gather distractors row-major (tf32-rounded)
// ---------------------------------------------------------------------------
__global__ void gather_distr_kernel() {
    int s = blockIdx.x;
    int c = threadIdx.x;
    int b = s / NPB;
    long long pix = (long long)b * HWW + g_yd[s] * WW + g_xd[s];
    g_B[s * DD + c] = to_tf32(g_des2t[pix * DD + c]);
}

// ---------------------------------------------------------------------------
// Per-sample: s_des1 gather, xy2+mask, pos(argmax)/neg scores, qlt, labels 0..12
// 2-way ILP over offsets to cover load + shfl-chain latency.
// ---------------------------------------------------------------------------
__global__ void score_kernel(const float* __restrict__ des1,
                             const float* __restrict__ qlt1,
                             const float* __restrict__ qlt2,
                             const float* __restrict__ aflow,
                             float* __restrict__ out) {
    int s = blockIdx.x;
    int c = threadIdx.x;
    int b = s / NPB;
    __shared__ float sdes[128];
    __shared__ float spall[32];
    __shared__ int sxy[2];

    int y1 = g_y1[s], x1 = g_x1[s];
    float v = des1[((b * DD + c) * HH + y1) * WW + x1];
    sdes[c] = v;
    g_A[s * DD + c] = to_tf32(v);

    if (c == 0) {
        float ax = aflow[((b * 2 + 0) * HH + y1) * WW + x1];
        float ay = aflow[((b * 2 + 1) * HH + y1) * WW + x1];
        int xi = (int)(ax + 0.5f);
        int yi = (int)(ay + 0.5f);
        sxy[0] = xi; sxy[1] = yi;
        g_x2[s] = xi; g_y2[s] = yi;
        out[MASK_OFF + s] = (xi >= 0 && yi >= 0 && xi < WW && yi < HH) ? 1.0f : 0.0f;
    }
    if (c < 13) out[LABELS_OFF + (long long)s * COLSZ + c] = (c == 0) ? 1.0f : 0.0f;
    __syncthreads();

    int x2 = sxy[0], y2 = sxy[1];
    int w = c >> 5, l = c & 31;
    float4 a = *(const float4*)&sdes[l * 4];
    const float* dt = g_des2t + (long long)b * HWW * DD;

    // pos offsets: warp w handles p = w, w+4, ...; process two per round (ILP)
    for (int p = w; p < PP; p += 8) {
        int p2 = p + 4;
        bool has2 = p2 < PP;
        int xx1 = min(max(x2 + c_pos[p].x, 0), WW - 1);
        int yy1 = min(max(y2 + c_pos[p].y, 0), HH - 1);
        int i2 = has2 ? p2 : p;
        int xx2 = min(max(x2 + c_pos[i2].x, 0), WW - 1);
        int yy2 = min(max(y2 + c_pos[i2].y, 0), HH - 1);
        float4 d1 = *(const float4*)(dt + (yy1 * WW + xx1) * DD + l * 4);
        float4 d2 = *(const float4*)(dt + (yy2 * WW + xx2) * DD + l * 4);
        float s1 = a.x * d1.x + a.y * d1.y + a.z * d1.z + a.w * d1.w;
        float s2 = a.x * d2.x + a.y * d2.y + a.z * d2.z + a.w * d2.w;
        #pragma unroll
        for (int o = 16; o > 0; o >>= 1) {
            s1 += __shfl_down_sync(0xffffffffu, s1, o);
            s2 += __shfl_down_sync(0xffffffffu, s2, o);
        }
        if (l == 0) {
            spall[p] = s1;
            if (has2) spall[p2] = s2;
        }
    }
    // neg offsets: q = w, w+4, w+8
    for (int q = w; q < QQ; q += 8) {
        int q2 = q + 4;
        bool has2 = q2 < QQ;
        int xx1 = min(max(x2 + c_neg[q].x, 0), WW - 1);
        int yy1 = min(max(y2 + c_neg[q].y, 0), HH - 1);
        int i2 = has2 ? q2 : q;
        int xx2 = min(max(x2 + c_neg[i2].x, 0), WW - 1);
        int yy2 = min(max(y2 + c_neg[i2].y, 0), HH - 1);
        float4 d1 = *(const float4*)(dt + (yy1 * WW + xx1) * DD + l * 4);
        float4 d2 = *(const float4*)(dt + (yy2 * WW + xx2) * DD + l * 4);
        float s1 = a.x * d1.x + a.y * d1.y + a.z * d1.z + a.w * d1.w;
        float s2 = a.x * d2.x + a.y * d2.y + a.z * d2.z + a.w * d2.w;
        #pragma unroll
        for (int o = 16; o > 0; o >>= 1) {
            s1 += __shfl_down_sync(0xffffffffu, s1, o);
            s2 += __shfl_down_sync(0xffffffffu, s2, o);
        }
        if (l == 0) {
            out[(long long)s * COLSZ + 1 + q] = s1;
            if (has2) out[(long long)s * COLSZ + 1 + q2] = s2;
        }
    }
    __syncthreads();

    if (c == 0) {
        float best = spall[0]; int bp = 0;
        #pragma unroll
        for (int p = 1; p < PP; p++) {
            if (spall[p] > best) { best = spall[p]; bp = p; }
        }
        out[(long long)s * COLSZ] = best;
        int selx = min(max(x2 + c_pos[bp].x, 0), WW - 1);
        int sely = min(max(y2 + c_pos[bp].y, 0), HH - 1);
        float q1 = qlt1[(long long)b * HWW + y1 * WW + x1];
        float q2 = qlt2[(long long)b * HWW + sely * WW + selx];
        out[QLT_OFF + s] = 0.5f * (q1 + q2);
    }
}

// ---------------------------------------------------------------------------
// dscores GEMM via mma.sync tf32 (m16n8k8). CTA tile 128x128, 8 warps 2x4,
// warp tile 64x32 (4x4 mma tiles). K chunks of 32 with register prefetch.
// Grid exactly 49x49 (NN = 49*128): no bounds guards.
// Epilogue: dis2 mask + streaming scores stores; labels via coalesced loop.
// ---------------------------------------------------------------------------
__global__ void __launch_bounds__(256) gemm_kernel(float* __restrict__ out) {
    __shared__ float As[128][36];   // [m][k], stride 36: frag loads conflict-free
    __shared__ float Bs[128][36];   // [n][k]
    __shared__ int sqx[128], sqy[128], sqb[128];

    int tid = threadIdx.x;
    int wid = tid >> 5, lane = tid & 31;
    int gid = lane >> 2, t4 = lane & 3;
    int wr = wid >> 2, wc = wid & 3;
    int m0 = blockIdx.y * 128, n0 = blockIdx.x * 128;

    if (tid < 128) {
        int q = n0 + tid;
        sqx[tid] = g_xd[q]; sqy[tid] = g_yd[q]; sqb[tid] = q / NPB;
    }

    float4 ra[4], rbv[4];
    #pragma unroll
    for (int i = 0; i < 4; i++) {
        int idx = tid + 256 * i;
        int row = idx >> 3, c4 = idx & 7;
        ra[i]  = *(const float4*)&g_A[(m0 + row) * DD + c4 * 4];
        rbv[i] = *(const float4*)&g_B[(n0 + row) * DD + c4 * 4];
    }

    float acc[4][4][4];
    #pragma unroll
    for (int i = 0; i < 4; i++)
        #pragma unroll
        for (int j = 0; j < 4; j++)
            #pragma unroll
            for (int c = 0; c < 4; c++) acc[i][j][c] = 0.0f;

    for (int kc = 0; kc < 4; kc++) {
        #pragma unroll
        for (int i = 0; i < 4; i++) {
            int idx = tid + 256 * i;
            int row = idx >> 3, c4 = idx & 7;
            *(float4*)&As[row][c4 * 4] = ra[i];
            *(float4*)&Bs[row][c4 * 4] = rbv[i];
        }
        __syncthreads();
        if (kc < 3) {
            #pragma unroll
            for (int i = 0; i < 4; i++) {
                int idx = tid + 256 * i;
                int row = idx >> 3, c4 = idx & 7;
                ra[i]  = *(const float4*)&g_A[(m0 + row) * DD + (kc + 1) * 32 + c4 * 4];
                rbv[i] = *(const float4*)&g_B[(n0 + row) * DD + (kc + 1) * 32 + c4 * 4];
            }
        }
        #pragma unroll
        for (int kk = 0; kk < 4; kk++) {
            int kb = kk * 8;
            uint32_t af[4][4], bf[4][2];
            #pragma unroll
            for (int i = 0; i < 4; i++) {
                int r = wr * 64 + i * 16 + gid;
                af[i][0] = __float_as_uint(As[r][kb + t4]);
                af[i][1] = __float_as_uint(As[r + 8][kb + t4]);
                af[i][2] = __float_as_uint(As[r][kb + t4 + 4]);
                af[i][3] = __float_as_uint(As[r + 8][kb + t4 + 4]);
            }
            #pragma unroll
            for (int j = 0; j < 4; j++) {
                int nr = wc * 32 + j * 8 + gid;
                bf[j][0] = __float_as_uint(Bs[nr][kb + t4]);
                bf[j][1] = __float_as_uint(Bs[nr][kb + t4 + 4]);
            }
            #pragma unroll
            for (int i = 0; i < 4; i++)
                #pragma unroll
                for (int j = 0; j < 4; j++)
                    mma_tf32(acc[i][j], af[i], bf[j]);
        }
        __syncthreads();
    }

    // Epilogue 1: scores with dis2 mask (streaming stores)
    #pragma unroll
    for (int i = 0; i < 4; i++) {
        int r0 = m0 + wr * 64 + i * 16 + gid;
        int r1 = r0 + 8;
        int rx0 = g_x2[r0], ry0 = g_y2[r0], rb0 = r0 / NPB;
        int rx1 = g_x2[r1], ry1 = g_y2[r1], rb1 = r1 / NPB;
        long long s0 = (long long)r0 * COLSZ + 13 + n0;
        long long s1 = (long long)r1 * COLSZ + 13 + n0;
        #pragma unroll
        for (int j = 0; j < 4; j++) {
            int c0 = wc * 32 + j * 8 + t4 * 2;
            int c1 = c0 + 1;
            int dx, dy, d2;
            dx = sqx[c0] - rx0; dy = sqy[c0] - ry0;
            d2 = dx * dx + dy * dy + ((sqb[c0] != rb0) ? 9 : 0);
            __stcs(&out[s0 + c0], (d2 < 9) ? 0.0f : acc[i][j][0]);
            dx = sqx[c1] - rx0; dy = sqy[c1] - ry0;
            d2 = dx * dx + dy * dy + ((sqb[c1] != rb0) ? 9 : 0);
            __stcs(&out[s0 + c1], (d2 < 9) ? 0.0f : acc[i][j][1]);
            dx = sqx[c0] - rx1; dy = sqy[c0] - ry1;
            d2 = dx * dx + dy * dy + ((sqb[c0] != rb1) ? 9 : 0);
            __stcs(&out[s1 + c0], (d2 < 9) ? 0.0f : acc[i][j][2]);
            dx = sqx[c1] - rx1; dy = sqy[c1] - ry1;
            d2 = dx * dx + dy * dy + ((sqb[c1] != rb1) ? 9 : 0);
            __stcs(&out[s1 + c1], (d2 < 9) ? 0.0f : acc[i][j][3]);
        }
    }

    // Epilogue 2: labels zeros for this 128x128 block, fully coalesced.
    // 256 threads: 2 rows per iter, col = tid & 127.
    {
        int ccol = tid & 127;
        int rh = tid >> 7;   // 0 or 1
        #pragma unroll
        for (int it = 0; it < 64; it++) {
            int r = m0 + it * 2 + rh;
            __stcs(&out[LABELS_OFF + (long long)r * COLSZ + 13 + n0 + ccol], 0.0f);
        }
    }
}

extern "C" void kernel_launch(void* const* d_in, const int* in_sizes, int n_in,
                              void* d_out, int out_size) {
    const float* des1  = (const float*)d_in[0];
    const float* det1  = (const float*)d_in[1];
    const float* qlt1  = (const float*)d_in[2];
    const float* des2  = (const float*)d_in[3];
    const float* det2  = (const float*)d_in[4];
    const float* qlt2  = (const float*)d_in[5];
    const float* aflow = (const float*)d_in[6];
    float* out = (float*)d_out;

    sample_kernel<<<(2 * NN + 255) / 256, 256>>>(det1, det2);
    transpose_kernel<<<dim3(HWW / 32, BB), 256>>>(des2);
    gather_distr_kernel<<<NN, 128>>>();
    score_kernel<<<NN, 128>>>(des1, qlt1, qlt2, aflow, out);
    gemm_kernel<<<dim3(49, 49), 256>>>(out);
}

// round 7
// speedup vs baseline: 2.0761x; 1.1764x over previous
#include <cuda_runtime.h>
#include <cstdint>

#define BB 8
#define DD 128
#define HH 256
#define WW 256
#define HWW 65536
#define TT 16
#define HCC 28
#define NPB 784
#define NN 6272
#define PP 29
#define QQ 12
#define COLSZ 6285

#define LABELS_OFF ((long long)NN * COLSZ)
#define MASK_OFF   (2LL * NN * COLSZ)
#define QLT_OFF    (2LL * NN * COLSZ + NN)

__device__ __forceinline__ float to_tf32(float x) {
    float r;
    asm("cvt.rna.tf32.f32 %0, %1;" : "=f"(r) : "f"(x));
    return r;
}

__device__ __forceinline__ void mma_tf32(float c[4], const uint32_t a[4], const uint32_t b[2]) {
    asm volatile(
        "mma.sync.aligned.m16n8k8.row.col.f32.tf32.tf32.f32 "
        "{%0,%1,%2,%3}, {%4,%5,%6,%7}, {%8,%9}, {%0,%1,%2,%3};"
        : "+f"(c[0]), "+f"(c[1]), "+f"(c[2]), "+f"(c[3])
        : "r"(a[0]), "r"(a[1]), "r"(a[2]), "r"(a[3]), "r"(b[0]), "r"(b[1]));
}

__device__ __forceinline__ uint32_t smem_u32(const void* p) {
    uint32_t a;
    asm("{ .reg .u64 t; cvta.to.shared.u64 t, %1; cvt.u32.u64 %0, t; }" : "=r"(a) : "l"(p));
    return a;
}
__device__ __forceinline__ void cp16(uint32_t dst, const float* src) {
    asm volatile("cp.async.cg.shared.global [%0], [%1], 16;"
                 :: "r"(dst), "l"(__cvta_generic_to_global(src)) : "memory");
}
#define CP_COMMIT() asm volatile("cp.async.commit_group;" ::: "memory")
#define CP_WAIT(n)  asm volatile("cp.async.wait_group %0;" :: "n"(n) : "memory")

// ===================== problem constants =====================
__constant__ int2 c_pos[PP] = {
    {-3,0},
    {-2,-2},{-2,-1},{-2,0},{-2,1},{-2,2},
    {-1,-2},{-1,-1},{-1,0},{-1,1},{-1,2},
    {0,-3},{0,-2},{0,-1},{0,0},{0,1},{0,2},{0,3},
    {1,-2},{1,-1},{1,0},{1,1},{1,2},
    {2,-2},{2,-1},{2,0},{2,1},{2,2},
    {3,0}
};
__constant__ int2 c_neg[QQ] = {
    {-8,0},{-6,-4},{-6,4},{-4,-6},{-4,6},
    {0,-8},{0,8},
    {4,-6},{4,6},{6,-4},{6,4},{8,0}
};

__device__ int g_y1[NN], g_x1[NN];
__device__ int g_yd[NN], g_xd[NN];
__device__ int g_x2[NN], g_y2[NN];
__device__ __align__(16) float g_A[NN * DD];     // s_des1 row-major [n][k], tf32-rounded
__device__ __align__(16) float g_B[NN * DD];     // distr   row-major [q][k], tf32-rounded
__device__ __align__(16) float g_des2t[(long long)BB * HWW * DD];  // des2 NHWC

// ---------------------------------------------------------------------------
// Cell argmax sampling (first-max). Reference swaps x/y on unpack.
// ---------------------------------------------------------------------------
__global__ void sample_kernel(const float* __restrict__ det1,
                              const float* __restrict__ det2) {
    int t = blockIdx.x * blockDim.x + threadIdx.x;
    if (t >= 2 * NN) return;
    const float* det = (t < NN) ? det1 : det2;
    int s = (t < NN) ? t : (t - NN);
    int b = s / NPB;
    int r = s - b * NPB;
    int cy = r / HCC;
    int cx = r - cy * HCC;
    const float* base = det + (long long)b * HWW + (TT + cy * 8) * WW + (TT + cx * 8);
    float best = -__int_as_float(0x7f800000);
    int bi = 0, bj = 0;
    #pragma unroll
    for (int ii = 0; ii < 8; ii++) {
        #pragma unroll
        for (int jj = 0; jj < 8; jj++) {
            float v = base[ii * WW + jj];
            if (v > best) { best = v; bi = ii; bj = jj; }
        }
    }
    int y = TT + cx * 8 + bj;   // reference swap
    int x = TT + cy * 8 + bi;
    if (t < NN) { g_y1[s] = y; g_x1[s] = x; }
    else        { g_yd[s] = y; g_xd[s] = x; }
}

// ---------------------------------------------------------------------------
// Transpose des2 (B,C,H,W) -> NHWC. __ldcs: single-use streaming reads.
// ---------------------------------------------------------------------------
__global__ void __launch_bounds__(256) transpose_kernel(const float* __restrict__ des2) {
    __shared__ float t[128][33];
    int b = blockIdx.y;
    int p0 = blockIdx.x * 32;
    int w = threadIdx.x >> 5, l = threadIdx.x & 31;
    const float* src = des2 + (long long)b * DD * HWW + p0;
    #pragma unroll
    for (int i = 0; i < 16; i++) {
        int cch = w + 8 * i;
        t[cch][l] = __ldcs(&src[(long long)cch * HWW + l]);
    }
    __syncthreads();
    float* dst = g_des2t + ((long long)b * HWW + p0) * DD;
    #pragma unroll
    for (int j = 0; j < 4; j++) {
        int p = w + 8 * j;
        #pragma unroll
        for (int u = 0; u < 4; u++) {
            dst[p * DD + u * 32 + l] = t[u * 32 + l][p];
        }
    }
}

// ---------------------------------------------------------------------------
// Gather distractors row-major (tf32-rounded)
// ---------------------------------------------------------------------------
__global__ void gather_distr_kernel() {
    int s = blockIdx.x;
    int c = threadIdx.x;
    int b = s / NPB;
    long long pix = (long long)b * HWW + g_yd[s] * WW + g_xd[s];
    g_B[s * DD + c] = to_tf32(g_des2t[pix * DD + c]);
}

// ---------------------------------------------------------------------------
// Per-sample: s_des1 gather, xy2+mask, pos(argmax)/neg scores, qlt, labels 0..12
// 4-way ILP over offsets to cover load + shfl-chain latency.
// ---------------------------------------------------------------------------
__global__ void score_kernel(const float* __restrict__ des1,
                             const float* __restrict__ qlt1,
                             const float* __restrict__ qlt2,
                             const float* __restrict__ aflow,
                             float* __restrict__ out) {
    int s = blockIdx.x;
    int c = threadIdx.x;
    int b = s / NPB;
    __shared__ float sdes[128];
    __shared__ float spall[32];
    __shared__ int sxy[2];

    int y1 = g_y1[s], x1 = g_x1[s];
    float v = des1[((b * DD + c) * HH + y1) * WW + x1];
    sdes[c] = v;
    g_A[s * DD + c] = to_tf32(v);

    if (c == 0) {
        float ax = aflow[((b * 2 + 0) * HH + y1) * WW + x1];
        float ay = aflow[((b * 2 + 1) * HH + y1) * WW + x1];
        int xi = (int)(ax + 0.5f);
        int yi = (int)(ay + 0.5f);
        sxy[0] = xi; sxy[1] = yi;
        g_x2[s] = xi; g_y2[s] = yi;
        out[MASK_OFF + s] = (xi >= 0 && yi >= 0 && xi < WW && yi < HH) ? 1.0f : 0.0f;
    }
    if (c < 13) out[LABELS_OFF + (long long)s * COLSZ + c] = (c == 0) ? 1.0f : 0.0f;
    __syncthreads();

    int x2 = sxy[0], y2 = sxy[1];
    int w = c >> 5, l = c & 31;
    float4 a = *(const float4*)&sdes[l * 4];
    const float* dt = g_des2t + (long long)b * HWW * DD;

    // pos offsets: warp w handles p = w + 4u; 4-way ILP batches
    for (int base = w; base < PP; base += 16) {
        int pi[4];
        float sum[4];
        float4 dv[4];
        #pragma unroll
        for (int u = 0; u < 4; u++) {
            int p = base + 4 * u;
            pi[u] = (p < PP) ? p : base;
        }
        #pragma unroll
        for (int u = 0; u < 4; u++) {
            int xx = min(max(x2 + c_pos[pi[u]].x, 0), WW - 1);
            int yy = min(max(y2 + c_pos[pi[u]].y, 0), HH - 1);
            dv[u] = *(const float4*)(dt + (yy * WW + xx) * DD + l * 4);
        }
        #pragma unroll
        for (int u = 0; u < 4; u++)
            sum[u] = a.x * dv[u].x + a.y * dv[u].y + a.z * dv[u].z + a.w * dv[u].w;
        #pragma unroll
        for (int o = 16; o > 0; o >>= 1) {
            #pragma unroll
            for (int u = 0; u < 4; u++)
                sum[u] += __shfl_down_sync(0xffffffffu, sum[u], o);
        }
        if (l == 0) {
            #pragma unroll
            for (int u = 0; u < 4; u++) {
                int p = base + 4 * u;
                if (p < PP) spall[p] = sum[u];
            }
        }
    }
    // neg offsets: q = w + 4u, u<4 (only 3 valid per warp; slot 3 duplicated)
    {
        int qi[4];
        float sum[4];
        float4 dv[4];
        #pragma unroll
        for (int u = 0; u < 4; u++) {
            int q = w + 4 * u;
            qi[u] = (q < QQ) ? q : w;
        }
        #pragma unroll
        for (int u = 0; u < 4; u++) {
            int xx = min(max(x2 + c_neg[qi[u]].x, 0), WW - 1);
            int yy = min(max(y2 + c_neg[qi[u]].y, 0), HH - 1);
            dv[u] = *(const float4*)(dt + (yy * WW + xx) * DD + l * 4);
        }
        #pragma unroll
        for (int u = 0; u < 4; u++)
            sum[u] = a.x * dv[u].x + a.y * dv[u].y + a.z * dv[u].z + a.w * dv[u].w;
        #pragma unroll
        for (int o = 16; o > 0; o >>= 1) {
            #pragma unroll
            for (int u = 0; u < 4; u++)
                sum[u] += __shfl_down_sync(0xffffffffu, sum[u], o);
        }
        if (l == 0) {
            #pragma unroll
            for (int u = 0; u < 4; u++) {
                int q = w + 4 * u;
                if (q < QQ) out[(long long)s * COLSZ + 1 + q] = sum[u];
            }
        }
    }
    __syncthreads();

    if (c == 0) {
        float best = spall[0]; int bp = 0;
        #pragma unroll
        for (int p = 1; p < PP; p++) {
            if (spall[p] > best) { best = spall[p]; bp = p; }
        }
        out[(long long)s * COLSZ] = best;
        int selx = min(max(x2 + c_pos[bp].x, 0), WW - 1);
        int sely = min(max(y2 + c_pos[bp].y, 0), HH - 1);
        float q1 = qlt1[(long long)b * HWW + y1 * WW + x1];
        float q2 = qlt2[(long long)b * HWW + sely * WW + selx];
        out[QLT_OFF + s] = 0.5f * (q1 + q2);
    }
}

// ---------------------------------------------------------------------------
// dscores GEMM via mma.sync tf32 (m16n8k8). CTA tile 128x128, 8 warps 2x4,
// warp tile 64x32 (4x4 mma tiles). cp.async double-buffered K pipeline
// (4 chunks of 32), 2 CTAs/SM. Grid exactly 49x49.
// Epilogue: dis2 mask + streaming scores stores; labels via coalesced loop.
// ---------------------------------------------------------------------------
// Dynamic smem: 2 stages x (A 128x36 + B 128x36) floats = 2 * 36864 B
#define GSTAGE_B 36864
#define GSMEM_B  (2 * GSTAGE_B)

__global__ void __launch_bounds__(256, 2) gemm_kernel(float* __restrict__ out) {
    extern __shared__ char sm[];
    __shared__ int sqx[128], sqy[128], sqb[128];

    int tid = threadIdx.x;
    int wid = tid >> 5, lane = tid & 31;
    int gid = lane >> 2, t4 = lane & 3;
    int wr = wid >> 2, wc = wid & 3;
    int m0 = blockIdx.y * 128, n0 = blockIdx.x * 128;

    if (tid < 128) {
        int q = n0 + tid;
        sqx[tid] = g_xd[q]; sqy[tid] = g_yd[q]; sqb[tid] = q / NPB;
    }

    uint32_t sb = smem_u32(sm);
    int ldrow = tid >> 3, ldc4 = tid & 7;   // 32 rows per pass, 4 passes

    // issue chunk kc into stage st
    auto issue = [&](int st, int kc) {
        uint32_t so = sb + st * GSTAGE_B;
        #pragma unroll
        for (int i = 0; i < 4; i++) {
            int row = ldrow + 32 * i;
            cp16(so + row * 144 + ldc4 * 16, &g_A[(m0 + row) * DD + kc * 32 + ldc4 * 4]);
            cp16(so + 18432 + row * 144 + ldc4 * 16, &g_B[(n0 + row) * DD + kc * 32 + ldc4 * 4]);
        }
        CP_COMMIT();
    };

    issue(0, 0);
    issue(1, 1);

    float acc[4][4][4];
    #pragma unroll
    for (int i = 0; i < 4; i++)
        #pragma unroll
        for (int j = 0; j < 4; j++)
            #pragma unroll
            for (int cc = 0; cc < 4; cc++) acc[i][j][cc] = 0.0f;

    #pragma unroll
    for (int kc = 0; kc < 4; kc++) {
        if (kc < 3) { CP_WAIT(1); } else { CP_WAIT(0); }
        __syncthreads();

        const float* As = (const float*)(sm + (kc & 1) * GSTAGE_B);
        const float* Bsp = As + 4608;

        #pragma unroll
        for (int kk = 0; kk < 4; kk++) {
            int kb = kk * 8;
            uint32_t af[4][4], bf[4][2];
            #pragma unroll
            for (int i = 0; i < 4; i++) {
                int r = wr * 64 + i * 16 + gid;
                af[i][0] = __float_as_uint(As[r * 36 + kb + t4]);
                af[i][1] = __float_as_uint(As[(r + 8) * 36 + kb + t4]);
                af[i][2] = __float_as_uint(As[r * 36 + kb + t4 + 4]);
                af[i][3] = __float_as_uint(As[(r + 8) * 36 + kb + t4 + 4]);
            }
            #pragma unroll
            for (int j = 0; j < 4; j++) {
                int nr = wc * 32 + j * 8 + gid;
                bf[j][0] = __float_as_uint(Bsp[nr * 36 + kb + t4]);
                bf[j][1] = __float_as_uint(Bsp[nr * 36 + kb + t4 + 4]);
            }
            #pragma unroll
            for (int i = 0; i < 4; i++)
                #pragma unroll
                for (int j = 0; j < 4; j++)
                    mma_tf32(acc[i][j], af[i], bf[j]);
        }

        if (kc + 2 < 4) {
            __syncthreads();          // stage kc&1 consumed by all warps
            issue(kc & 1, kc + 2);    // overlap with compute of chunk kc+1
        }
    }

    // Epilogue 1: scores with dis2 mask (streaming stores)
    #pragma unroll
    for (int i = 0; i < 4; i++) {
        int r0 = m0 + wr * 64 + i * 16 + gid;
        int r1 = r0 + 8;
        int rx0 = g_x2[r0], ry0 = g_y2[r0], rb0 = r0 / NPB;
        int rx1 = g_x2[r1], ry1 = g_y2[r1], rb1 = r1 / NPB;
        long long s0 = (long long)r0 * COLSZ + 13 + n0;
        long long s1 = (long long)r1 * COLSZ + 13 + n0;
        #pragma unroll
        for (int j = 0; j < 4; j++) {
            int c0 = wc * 32 + j * 8 + t4 * 2;
            int c1 = c0 + 1;
            int dx, dy, d2;
            dx = sqx[c0] - rx0; dy = sqy[c0] - ry0;
            d2 = dx * dx + dy * dy + ((sqb[c0] != rb0) ? 9 : 0);
            __stcs(&out[s0 + c0], (d2 < 9) ? 0.0f : acc[i][j][0]);
            dx = sqx[c1] - rx0; dy = sqy[c1] - ry0;
            d2 = dx * dx + dy * dy + ((sqb[c1] != rb0) ? 9 : 0);
            __stcs(&out[s0 + c1], (d2 < 9) ? 0.0f : acc[i][j][1]);
            dx = sqx[c0] - rx1; dy = sqy[c0] - ry1;
            d2 = dx * dx + dy * dy + ((sqb[c0] != rb1) ? 9 : 0);
            __stcs(&out[s1 + c0], (d2 < 9) ? 0.0f : acc[i][j][2]);
            dx = sqx[c1] - rx1; dy = sqy[c1] - ry1;
            d2 = dx * dx + dy * dy + ((sqb[c1] != rb1) ? 9 : 0);
            __stcs(&out[s1 + c1], (d2 < 9) ? 0.0f : acc[i][j][3]);
        }
    }

    // Epilogue 2: labels zeros for this 128x128 block, fully coalesced.
    {
        int ccol = tid & 127;
        int rh = tid >> 7;   // 0 or 1
        #pragma unroll
        for (int it = 0; it < 64; it++) {
            int r = m0 + it * 2 + rh;
            __stcs(&out[LABELS_OFF + (long long)r * COLSZ + 13 + n0 + ccol], 0.0f);
        }
    }
}

extern "C" void kernel_launch(void* const* d_in, const int* in_sizes, int n_in,
                              void* d_out, int out_size) {
    const float* des1  = (const float*)d_in[0];
    const float* det1  = (const float*)d_in[1];
    const float* qlt1  = (const float*)d_in[2];
    const float* des2  = (const float*)d_in[3];
    const float* det2  = (const float*)d_in[4];
    const float* qlt2  = (const float*)d_in[5];
    const float* aflow = (const float*)d_in[6];
    float* out = (float*)d_out;

    cudaFuncSetAttribute(gemm_kernel, cudaFuncAttributeMaxDynamicSharedMemorySize, GSMEM_B);

    sample_kernel<<<(2 * NN + 255) / 256, 256>>>(det1, det2);
    transpose_kernel<<<dim3(HWW / 32, BB), 256>>>(des2);
    gather_distr_kernel<<<NN, 128>>>();
    score_kernel<<<NN, 128>>>(des1, qlt1, qlt2, aflow, out);
    gemm_kernel<<<dim3(49, 49), 256, GSMEM_B>>>(out);
}

// round 9
// speedup vs baseline: 2.1059x; 1.0143x over previous
#include <cuda_runtime.h>
#include <cstdint>

#define BB 8
#define DD 128
#define HH 256
#define WW 256
#define HWW 65536
#define TT 16
#define HCC 28
#define NPB 784
#define NN 6272
#define PP 29
#define QQ 12
#define COLSZ 6285

#define LABELS_OFF ((long long)NN * COLSZ)
#define MASK_OFF   (2LL * NN * COLSZ)
#define QLT_OFF    (2LL * NN * COLSZ + NN)

__device__ __forceinline__ float to_tf32(float x) {
    float r;
    asm("cvt.rna.tf32.f32 %0, %1;" : "=f"(r) : "f"(x));
    return r;
}

__device__ __forceinline__ void mma_tf32(float c[4], const uint32_t a[4], const uint32_t b[2]) {
    asm volatile(
        "mma.sync.aligned.m16n8k8.row.col.f32.tf32.tf32.f32 "
        "{%0,%1,%2,%3}, {%4,%5,%6,%7}, {%8,%9}, {%0,%1,%2,%3};"
        : "+f"(c[0]), "+f"(c[1]), "+f"(c[2]), "+f"(c[3])
        : "r"(a[0]), "r"(a[1]), "r"(a[2]), "r"(a[3]), "r"(b[0]), "r"(b[1]));
}

__device__ __forceinline__ uint32_t smem_u32(const void* p) {
    uint32_t a;
    asm("{ .reg .u64 t; cvta.to.shared.u64 t, %1; cvt.u32.u64 %0, t; }" : "=r"(a) : "l"(p));
    return a;
}
__device__ __forceinline__ void cp16(uint32_t dst, const float* src) {
    asm volatile("cp.async.cg.shared.global [%0], [%1], 16;"
                 :: "r"(dst), "l"(__cvta_generic_to_global(src)) : "memory");
}
#define CP_COMMIT() asm volatile("cp.async.commit_group;" ::: "memory")
#define CP_WAIT(n)  asm volatile("cp.async.wait_group %0;" :: "n"(n) : "memory")

// ===================== problem constants =====================
__constant__ int2 c_pos[PP] = {
    {-3,0},
    {-2,-2},{-2,-1},{-2,0},{-2,1},{-2,2},
    {-1,-2},{-1,-1},{-1,0},{-1,1},{-1,2},
    {0,-3},{0,-2},{0,-1},{0,0},{0,1},{0,2},{0,3},
    {1,-2},{1,-1},{1,0},{1,1},{1,2},
    {2,-2},{2,-1},{2,0},{2,1},{2,2},
    {3,0}
};
__constant__ int2 c_neg[QQ] = {
    {-8,0},{-6,-4},{-6,4},{-4,-6},{-4,6},
    {0,-8},{0,8},
    {4,-6},{4,6},{6,-4},{6,4},{8,0}
};

__device__ int g_y1[NN], g_x1[NN];
__device__ int g_yd[NN], g_xd[NN];
__device__ int g_x2[NN], g_y2[NN];
__device__ __align__(16) float g_A[NN * DD];     // s_des1 row-major [n][k], tf32-rounded
__device__ __align__(16) float g_B[NN * DD];     // distr   row-major [q][k], tf32-rounded
__device__ __align__(16) float g_des2t[(long long)BB * HWW * DD];  // des2 NHWC

// ---------------------------------------------------------------------------
// Cell argmax sampling (first-max). Reference swaps x/y on unpack.
// ---------------------------------------------------------------------------
__global__ void sample_kernel(const float* __restrict__ det1,
                              const float* __restrict__ det2) {
    int t = blockIdx.x * blockDim.x + threadIdx.x;
    if (t >= 2 * NN) return;
    const float* det = (t < NN) ? det1 : det2;
    int s = (t < NN) ? t : (t - NN);
    int b = s / NPB;
    int r = s - b * NPB;
    int cy = r / HCC;
    int cx = r - cy * HCC;
    const float* base = det + (long long)b * HWW + (TT + cy * 8) * WW + (TT + cx * 8);
    float best = -__int_as_float(0x7f800000);
    int bi = 0, bj = 0;
    #pragma unroll
    for (int ii = 0; ii < 8; ii++) {
        #pragma unroll
        for (int jj = 0; jj < 8; jj++) {
            float v = base[ii * WW + jj];
            if (v > best) { best = v; bi = ii; bj = jj; }
        }
    }
    int y = TT + cx * 8 + bj;   // reference swap
    int x = TT + cy * 8 + bi;
    if (t < NN) { g_y1[s] = y; g_x1[s] = x; }
    else        { g_yd[s] = y; g_xd[s] = x; }
}

// ---------------------------------------------------------------------------
// Transpose des2 (B,C,H,W) -> NHWC. __ldcs: single-use streaming reads.
// ---------------------------------------------------------------------------
__global__ void __launch_bounds__(256) transpose_kernel(const float* __restrict__ des2) {
    __shared__ float t[128][33];
    int b = blockIdx.y;
    int p0 = blockIdx.x * 32;
    int w = threadIdx.x >> 5, l = threadIdx.x & 31;
    const float* src = des2 + (long long)b * DD * HWW + p0;
    #pragma unroll
    for (int i = 0; i < 16; i++) {
        int cch = w + 8 * i;
        t[cch][l] = __ldcs(&src[(long long)cch * HWW + l]);
    }
    __syncthreads();
    float* dst = g_des2t + ((long long)b * HWW + p0) * DD;
    #pragma unroll
    for (int j = 0; j < 4; j++) {
        int p = w + 8 * j;
        #pragma unroll
        for (int u = 0; u < 4; u++) {
            dst[p * DD + u * 32 + l] = t[u * 32 + l][p];
        }
    }
}

// ---------------------------------------------------------------------------
// Per-sample: s_des1 gather, distractor gather (fused), xy2+mask,
// pos(argmax)/neg scores, qlt, labels col 0. 4-way ILP over offsets.
// ---------------------------------------------------------------------------
__global__ void score_kernel(const float* __restrict__ des1,
                             const float* __restrict__ qlt1,
                             const float* __restrict__ qlt2,
                             const float* __restrict__ aflow,
                             float* __restrict__ out) {
    int s = blockIdx.x;
    int c = threadIdx.x;
    int b = s / NPB;
    __shared__ float sdes[128];
    __shared__ float spall[32];
    __shared__ int sxy[2];

    int y1 = g_y1[s], x1 = g_x1[s];
    float v = des1[((b * DD + c) * HH + y1) * WW + x1];
    sdes[c] = v;
    g_A[s * DD + c] = to_tf32(v);

    // fused distractor gather (was gather_distr_kernel)
    {
        long long pixd = (long long)b * HWW + g_yd[s] * WW + g_xd[s];
        g_B[s * DD + c] = to_tf32(g_des2t[pixd * DD + c]);
    }

    if (c == 0) {
        float ax = aflow[((b * 2 + 0) * HH + y1) * WW + x1];
        float ay = aflow[((b * 2 + 1) * HH + y1) * WW + x1];
        int xi = (int)(ax + 0.5f);
        int yi = (int)(ay + 0.5f);
        sxy[0] = xi; sxy[1] = yi;
        g_x2[s] = xi; g_y2[s] = yi;
        out[MASK_OFF + s] = (xi >= 0 && yi >= 0 && xi < WW && yi < HH) ? 1.0f : 0.0f;
        out[LABELS_OFF + (long long)s * COLSZ] = 1.0f;   // rest of labels zeroed by memset
    }
    __syncthreads();

    int x2 = sxy[0], y2 = sxy[1];
    int w = c >> 5, l = c & 31;
    float4 a = *(const float4*)&sdes[l * 4];
    const float* dt = g_des2t + (long long)b * HWW * DD;

    // pos offsets: warp w handles p = w + 4u; 4-way ILP batches
    for (int base = w; base < PP; base += 16) {
        int pi[4];
        float sum[4];
        float4 dv[4];
        #pragma unroll
        for (int u = 0; u < 4; u++) {
            int p = base + 4 * u;
            pi[u] = (p < PP) ? p : base;
        }
        #pragma unroll
        for (int u = 0; u < 4; u++) {
            int xx = min(max(x2 + c_pos[pi[u]].x, 0), WW - 1);
            int yy = min(max(y2 + c_pos[pi[u]].y, 0), HH - 1);
            dv[u] = *(const float4*)(dt + (yy * WW + xx) * DD + l * 4);
        }
        #pragma unroll
        for (int u = 0; u < 4; u++)
            sum[u] = a.x * dv[u].x + a.y * dv[u].y + a.z * dv[u].z + a.w * dv[u].w;
        #pragma unroll
        for (int o = 16; o > 0; o >>= 1) {
            #pragma unroll
            for (int u = 0; u < 4; u++)
                sum[u] += __shfl_down_sync(0xffffffffu, sum[u], o);
        }
        if (l == 0) {
            #pragma unroll
            for (int u = 0; u < 4; u++) {
                int p = base + 4 * u;
                if (p < PP) spall[p] = sum[u];
            }
        }
    }
    // neg offsets: q = w + 4u, u<4
    {
        int qi[4];
        float sum[4];
        float4 dv[4];
        #pragma unroll
        for (int u = 0; u < 4; u++) {
            int q = w + 4 * u;
            qi[u] = (q < QQ) ? q : w;
        }
        #pragma unroll
        for (int u = 0; u < 4; u++) {
            int xx = min(max(x2 + c_neg[qi[u]].x, 0), WW - 1);
            int yy = min(max(y2 + c_neg[qi[u]].y, 0), HH - 1);
            dv[u] = *(const float4*)(dt + (yy * WW + xx) * DD + l * 4);
        }
        #pragma unroll
        for (int u = 0; u < 4; u++)
            sum[u] = a.x * dv[u].x + a.y * dv[u].y + a.z * dv[u].z + a.w * dv[u].w;
        #pragma unroll
        for (int o = 16; o > 0; o >>= 1) {
            #pragma unroll
            for (int u = 0; u < 4; u++)
                sum[u] += __shfl_down_sync(0xffffffffu, sum[u], o);
        }
        if (l == 0) {
            #pragma unroll
            for (int u = 0; u < 4; u++) {
                int q = w + 4 * u;
                if (q < QQ) out[(long long)s * COLSZ + 1 + q] = sum[u];
            }
        }
    }
    __syncthreads();

    if (c == 0) {
        float best = spall[0]; int bp = 0;
        #pragma unroll
        for (int p = 1; p < PP; p++) {
            if (spall[p] > best) { best = spall[p]; bp = p; }
        }
        out[(long long)s * COLSZ] = best;
        int selx = min(max(x2 + c_pos[bp].x, 0), WW - 1);
        int sely = min(max(y2 + c_pos[bp].y, 0), HH - 1);
        float q1 = qlt1[(long long)b * HWW + y1 * WW + x1];
        float q2 = qlt2[(long long)b * HWW + sely * WW + selx];
        out[QLT_OFF + s] = 0.5f * (q1 + q2);
    }
}

// ---------------------------------------------------------------------------
// dscores GEMM via mma.sync tf32 (m16n8k8). CTA tile 128x128, 8 warps 2x4,
// warp tile 64x32. 3-stage cp.async pipeline (single barrier per chunk),
// 2 CTAs/SM. Grid exactly 49x49. Epilogue: dis2 mask + streaming stores.
// ---------------------------------------------------------------------------
#define GSTAGE_B 36864
#define GSMEM_B  (3 * GSTAGE_B)   // 110592 B

__global__ void __launch_bounds__(256, 2) gemm_kernel(float* __restrict__ out) {
    extern __shared__ char sm[];
    __shared__ int sqx[128], sqy[128], sqb[128];

    int tid = threadIdx.x;
    int wid = tid >> 5, lane = tid & 31;
    int gid = lane >> 2, t4 = lane & 3;
    int wr = wid >> 2, wc = wid & 3;
    int m0 = blockIdx.y * 128, n0 = blockIdx.x * 128;

    if (tid < 128) {
        int q = n0 + tid;
        sqx[tid] = g_xd[q]; sqy[tid] = g_yd[q]; sqb[tid] = q / NPB;
    }

    uint32_t sb = smem_u32(sm);
    int ldrow = tid >> 3, ldc4 = tid & 7;   // 32 rows per pass, 4 passes

    auto issue = [&](int st, int kc) {
        uint32_t so = sb + st * GSTAGE_B;
        #pragma unroll
        for (int i = 0; i < 4; i++) {
            int row = ldrow + 32 * i;
            cp16(so + row * 144 + ldc4 * 16, &g_A[(m0 + row) * DD + kc * 32 + ldc4 * 4]);
            cp16(so + 18432 + row * 144 + ldc4 * 16, &g_B[(n0 + row) * DD + kc * 32 + ldc4 * 4]);
        }
        CP_COMMIT();
    };

    issue(0, 0);
    issue(1, 1);

    float acc[4][4][4];
    #pragma unroll
    for (int i = 0; i < 4; i++)
        #pragma unroll
        for (int j = 0; j < 4; j++)
            #pragma unroll
            for (int cc = 0; cc < 4; cc++) acc[i][j][cc] = 0.0f;

    #pragma unroll
    for (int kc = 0; kc < 4; kc++) {
        if (kc < 3) { CP_WAIT(1); } else { CP_WAIT(0); }
        __syncthreads();

        // prefetch chunk kc+2 into stage (kc+2)%3 — that stage held chunk
        // kc-1, consumed by all warps before this iteration's barrier.
        if (kc + 2 < 4) issue((kc + 2) % 3, kc + 2);

        const float* As = (const float*)(sm + (kc % 3) * GSTAGE_B);
        const float* Bsp = As + 4608;

        #pragma unroll
        for (int kk = 0; kk < 4; kk++) {
            int kb = kk * 8;
            uint32_t af[4][4], bf[4][2];
            #pragma unroll
            for (int i = 0; i < 4; i++) {
                int r = wr * 64 + i * 16 + gid;
                af[i][0] = __float_as_uint(As[r * 36 + kb + t4]);
                af[i][1] = __float_as_uint(As[(r + 8) * 36 + kb + t4]);
                af[i][2] = __float_as_uint(As[r * 36 + kb + t4 + 4]);
                af[i][3] = __float_as_uint(As[(r + 8) * 36 + kb + t4 + 4]);
            }
            #pragma unroll
            for (int j = 0; j < 4; j++) {
                int nr = wc * 32 + j * 8 + gid;
                bf[j][0] = __float_as_uint(Bsp[nr * 36 + kb + t4]);
                bf[j][1] = __float_as_uint(Bsp[nr * 36 + kb + t4 + 4]);
            }
            #pragma unroll
            for (int i = 0; i < 4; i++)
                #pragma unroll
                for (int j = 0; j < 4; j++)
                    mma_tf32(acc[i][j], af[i], bf[j]);
        }
    }

    // Epilogue: scores with dis2 mask (streaming stores). Labels pre-zeroed.
    #pragma unroll
    for (int i = 0; i < 4; i++) {
        int r0 = m0 + wr * 64 + i * 16 + gid;
        int r1 = r0 + 8;
        int rx0 = g_x2[r0], ry0 = g_y2[r0], rb0 = r0 / NPB;
        int rx1 = g_x2[r1], ry1 = g_y2[r1], rb1 = r1 / NPB;
        long long s0 = (long long)r0 * COLSZ + 13 + n0;
        long long s1 = (long long)r1 * COLSZ + 13 + n0;
        #pragma unroll
        for (int j = 0; j < 4; j++) {
            int c0 = wc * 32 + j * 8 + t4 * 2;
            int c1 = c0 + 1;
            int dx, dy, d2;
            dx = sqx[c0] - rx0; dy = sqy[c0] - ry0;
            d2 = dx * dx + dy * dy + ((sqb[c0] != rb0) ? 9 : 0);
            __stcs(&out[s0 + c0], (d2 < 9) ? 0.0f : acc[i][j][0]);
            dx = sqx[c1] - rx0; dy = sqy[c1] - ry0;
            d2 = dx * dx + dy * dy + ((sqb[c1] != rb0) ? 9 : 0);
            __stcs(&out[s0 + c1], (d2 < 9) ? 0.0f : acc[i][j][1]);
            dx = sqx[c0] - rx1; dy = sqy[c0] - ry1;
            d2 = dx * dx + dy * dy + ((sqb[c0] != rb1) ? 9 : 0);
            __stcs(&out[s1 + c0], (d2 < 9) ? 0.0f : acc[i][j][2]);
            dx = sqx[c1] - rx1; dy = sqy[c1] - ry1;
            d2 = dx * dx + dy * dy + ((sqb[c1] != rb1) ? 9 : 0);
            __stcs(&out[s1 + c1], (d2 < 9) ? 0.0f : acc[i][j][3]);
        }
    }
}

extern "C" void kernel_launch(void* const* d_in, const int* in_sizes, int n_in,
                              void* d_out, int out_size) {
    const float* des1  = (const float*)d_in[0];
    const float* det1  = (const float*)d_in[1];
    const float* qlt1  = (const float*)d_in[2];
    const float* des2  = (const float*)d_in[3];
    const float* det2  = (const float*)d_in[4];
    const float* qlt2  = (const float*)d_in[5];
    const float* aflow = (const float*)d_in[6];
    float* out = (float*)d_out;

    cudaFuncSetAttribute(gemm_kernel, cudaFuncAttributeMaxDynamicSharedMemorySize, GSMEM_B);

    // Zero the labels plane up front (graph memset node); score sets col 0 = 1,
    // gemm no longer stores labels at all.
    cudaMemsetAsync(out + LABELS_OFF, 0, (size_t)NN * COLSZ * sizeof(float));

    sample_kernel<<<(2 * NN + 255) / 256, 256>>>(det1, det2);
    transpose_kernel<<<dim3(HWW / 32, BB), 256>>>(des2);
    score_kernel<<<NN, 128>>>(des1, qlt1, qlt2, aflow, out);
    gemm_kernel<<<dim3(49, 49), 256, GSMEM_B>>>(out);
}